// round 1
// baseline (speedup 1.0000x reference)
#include <cuda_runtime.h>
#include <math.h>

#define NN    10000
#define SS_   4
#define LL    8
#define BB    (SS_*NN)          // 40000 sequences
#define HH    128
#define G3    384               // 3*H
#define ORIG_ 64
#define SUBN  100
#define LOSS_BLOCKS (SS_*SUBN*(LL-1))   // 2800
#define CNT   (SS_*SUBN*(LL-1)*ORIG_)   // 179200

// ---------------- device scratch (static allocation is allowed) -------------
__device__ float g_T[LL*G3];            // one-hot input table: T[u][o] = Wih_w[o][u]+bih_w[o]
__device__ float g_W1t[HH*G3];          // Whh_w transposed [k][o]
__device__ float g_W2t[G3*G3];          // [Wih | Whh] transposed [k][o], k in [0,384)
__device__ float g_Wsst[HH*ORIG_];      // W_ss transposed [k][o]
__device__ float g_ywalk[(size_t)LL*BB*HH];        // walk-GRU outputs, all 8 steps
__device__ float g_yseq[(size_t)(LL-1)*BB*HH];     // main-GRU outputs, steps 0..6
__device__ float g_partA[LOSS_BLOCKS];
__device__ float g_partB[LOSS_BLOCKS];
__device__ float g_partY[LOSS_BLOCKS];

// ---------------- activations (accurate: ~1e-6 abs error) -------------------
__device__ __forceinline__ float sigmoidf_(float x) {
    return __fdividef(1.f, 1.f + __expf(-x));
}
__device__ __forceinline__ float tanhf_(float x) {
    // tanh(x) = 1 - 2/(e^{2x}+1); saturates correctly at +/-inf, small-x abs err ~1e-7
    return 1.f - 2.f * __fdividef(1.f, __expf(2.f * x) + 1.f);
}

// ---------------- prep: transposes + tables ---------------------------------
__global__ void prep_kernel(const float* __restrict__ Wih_w, const float* __restrict__ bih_w,
                            const float* __restrict__ Whh_w, const float* __restrict__ Wih,
                            const float* __restrict__ Whh,   const float* __restrict__ W_ss)
{
    int i = blockIdx.x * blockDim.x + threadIdx.x;
    if (i < LL*G3)  { int u = i / G3, o = i % G3; g_T[i]   = Wih_w[o*LL + u] + bih_w[o]; }
    if (i < HH*G3)  { int k = i / G3, o = i % G3; g_W1t[i] = Whh_w[o*HH + k]; }
    if (i < G3*G3)  { int k = i / G3, o = i % G3;
                      g_W2t[i] = (k < 256) ? Wih[o*256 + k] : Whh[o*HH + (k - 256)]; }
    if (i < HH*ORIG_){ int k = i / ORIG_, o = i % ORIG_; g_Wsst[i] = W_ss[o*HH + k]; }
}

// ---------------- phase 1: walk GRU (8 fused steps) --------------------------
// block: 32 sequences, 256 threads. thread = (my = tid>>5 in [0,8), ox = tid&31)
// thread owns m in {my*4..my*4+3}, output channels o = ox+32j, j in [0,12)
// smem: Hs[32][128] state | Ws[32][384] weight k-chunk | U[32][8] one-hot indices
#define SMEM1 ((32*128 + 32*384)*4 + 32*8*4)
__global__ void __launch_bounds__(256) walk_gru_kernel(
    const int* __restrict__ walks, const float* __restrict__ bhh_w)
{
    extern __shared__ float sm[];
    float* Hs = sm;                 // 32*128
    float* Ws = sm + 32*128;        // 32*384
    int*   U  = (int*)(Ws + 32*384);// 32*8
    const int tid  = threadIdx.x;
    const int ox   = tid & 31;
    const int my   = tid >> 5;
    const int seq0 = blockIdx.x * 32;

    for (int q = tid; q < 32*128; q += 256) Hs[q] = 0.f;   // h0 = 0

    { // uniqueness indices: U[m][t] = first occurrence of walks[7-t] within walk
        int m = tid >> 3, t = tid & 7;
        const int* w = walks + (size_t)(seq0 + m) * LL;
        int tgt = w[7 - t];
        int u = 0;
        #pragma unroll
        for (int j = 7; j >= 0; --j) if (w[j] == tgt) u = j;
        U[m*8 + t] = u;
    }

    float br[4], bz[4], bn[4];
    #pragma unroll
    for (int j = 0; j < 4; ++j) {
        int c = ox + 32*j;
        br[j] = bhh_w[c]; bz[j] = bhh_w[c + 128]; bn[j] = bhh_w[c + 256];
    }
    __syncthreads();

    for (int t = 0; t < LL; ++t) {
        float acc[4][12];
        #pragma unroll
        for (int i = 0; i < 4; ++i)
            #pragma unroll
            for (int j = 0; j < 12; ++j) acc[i][j] = 0.f;

        for (int kc = 0; kc < 4; ++kc) {
            __syncthreads();
            const float4* src = (const float4*)(g_W1t + kc*(32*G3));
            float4* dst = (float4*)Ws;
            #pragma unroll
            for (int q = 0; q < 12; ++q) dst[tid + 256*q] = src[tid + 256*q];
            __syncthreads();
            const int kbase = kc*32;
            #pragma unroll 2
            for (int kk = 0; kk < 32; ++kk) {
                const int k = kbase + kk;
                const float a0 = Hs[(my*4+0)*128 + k];
                const float a1 = Hs[(my*4+1)*128 + k];
                const float a2 = Hs[(my*4+2)*128 + k];
                const float a3 = Hs[(my*4+3)*128 + k];
                const float* wp = Ws + kk*G3 + ox;
                #pragma unroll
                for (int j = 0; j < 12; ++j) {
                    const float wv = wp[32*j];
                    acc[0][j] += a0*wv; acc[1][j] += a1*wv;
                    acc[2][j] += a2*wv; acc[3][j] += a3*wv;
                }
            }
        }
        __syncthreads();   // all FMA reads of Hs done before state update

        #pragma unroll
        for (int i = 0; i < 4; ++i) {
            const int m = my*4 + i;
            const int seq = seq0 + m;
            const float* Tp = g_T + U[m*8 + t]*G3;
            #pragma unroll
            for (int j = 0; j < 4; ++j) {
                const int c = ox + 32*j;
                float r  = sigmoidf_(acc[i][j]     + br[j] + Tp[c]);
                float z  = sigmoidf_(acc[i][j + 4] + bz[j] + Tp[c + 128]);
                float nn = tanhf_(Tp[c + 256] + r * (acc[i][j + 8] + bn[j]));
                float hv = Hs[m*128 + c];
                hv = (1.f - z)*nn + z*hv;
                Hs[m*128 + c] = hv;
                g_ywalk[(size_t)(t*BB + seq)*HH + c] = hv;
            }
        }
        // next chunk-load's __syncthreads orders these writes vs next-step reads
    }
}

// ---------------- phase 2: main GRU (8 fused steps) --------------------------
// x_cat = [ h[walks[7-t]] (128) | y_walk[t] (128) | state (128) ], W2t is [k][o]
// n-gate needs input-part and hidden-part separately (r multiplies hidden part).
#define SMEM2 ((32*384*2)*4 + 32*8*4)
__global__ void __launch_bounds__(256) main_gru_kernel(
    const int* __restrict__ walks, const float* __restrict__ hfeat,
    const float* __restrict__ bih, const float* __restrict__ bhh,
    float* __restrict__ out)
{
    extern __shared__ float sm[];
    float* Xs = sm;                  // 32*384: [input_h | y_walk | state]
    float* Ws = sm + 32*384;         // 32*384 weight k-chunk
    int*   wk = (int*)(Ws + 32*384); // 32*8 walk nodes
    const int tid  = threadIdx.x;
    const int ox   = tid & 31;
    const int my   = tid >> 5;
    const int seq0 = blockIdx.x * 32;

    { int m = tid >> 3, j = tid & 7; wk[m*8 + j] = walks[(size_t)(seq0 + m)*LL + j]; }

    // h0 = h_walk = y_walk[7]
    for (int q = tid; q < 32*128; q += 256) {
        int m = q >> 7, c = q & 127;
        Xs[m*G3 + 256 + c] = g_ywalk[(size_t)(7*BB + seq0 + m)*HH + c];
    }
    float br2[4], bz2[4], bin[4], bhn[4];
    #pragma unroll
    for (int j = 0; j < 4; ++j) {
        int c = ox + 32*j;
        br2[j] = bih[c]       + bhh[c];
        bz2[j] = bih[c + 128] + bhh[c + 128];
        bin[j] = bih[c + 256];
        bhn[j] = bhh[c + 256];
    }
    __syncthreads();

    for (int t = 0; t < LL; ++t) {
        // build inputs: gather h + y_walk[t] (state region untouched)
        for (int q = tid; q < 32*128; q += 256) {
            int m = q >> 7, c = q & 127;
            int node = wk[m*8 + 7 - t];
            Xs[m*G3 + c]       = hfeat[(size_t)node*HH + c];
            Xs[m*G3 + 128 + c] = g_ywalk[(size_t)(t*BB + seq0 + m)*HH + c];
        }
        float acc[4][12], accH[4][4];
        #pragma unroll
        for (int i = 0; i < 4; ++i) {
            #pragma unroll
            for (int j = 0; j < 12; ++j) acc[i][j] = 0.f;
            #pragma unroll
            for (int j = 0; j < 4;  ++j) accH[i][j] = 0.f;
        }

        for (int kc = 0; kc < 12; ++kc) {
            __syncthreads();
            const float4* src = (const float4*)(g_W2t + kc*(32*G3));
            float4* dst = (float4*)Ws;
            #pragma unroll
            for (int q = 0; q < 12; ++q) dst[tid + 256*q] = src[tid + 256*q];
            __syncthreads();
            const int kbase = kc*32;
            if (kc < 8) {                     // input part: all 384 outputs -> acc
                #pragma unroll 2
                for (int kk = 0; kk < 32; ++kk) {
                    const int k = kbase + kk;
                    const float a0 = Xs[(my*4+0)*G3 + k];
                    const float a1 = Xs[(my*4+1)*G3 + k];
                    const float a2 = Xs[(my*4+2)*G3 + k];
                    const float a3 = Xs[(my*4+3)*G3 + k];
                    const float* wp = Ws + kk*G3 + ox;
                    #pragma unroll
                    for (int j = 0; j < 12; ++j) {
                        const float wv = wp[32*j];
                        acc[0][j] += a0*wv; acc[1][j] += a1*wv;
                        acc[2][j] += a2*wv; acc[3][j] += a3*wv;
                    }
                }
            } else {                          // hidden part: n-range -> accH
                #pragma unroll 2
                for (int kk = 0; kk < 32; ++kk) {
                    const int k = kbase + kk;
                    const float a0 = Xs[(my*4+0)*G3 + k];
                    const float a1 = Xs[(my*4+1)*G3 + k];
                    const float a2 = Xs[(my*4+2)*G3 + k];
                    const float a3 = Xs[(my*4+3)*G3 + k];
                    const float* wp = Ws + kk*G3 + ox;
                    #pragma unroll
                    for (int j = 0; j < 8; ++j) {
                        const float wv = wp[32*j];
                        acc[0][j] += a0*wv; acc[1][j] += a1*wv;
                        acc[2][j] += a2*wv; acc[3][j] += a3*wv;
                    }
                    #pragma unroll
                    for (int j = 0; j < 4; ++j) {
                        const float wv = wp[32*(8 + j)];
                        accH[0][j] += a0*wv; accH[1][j] += a1*wv;
                        accH[2][j] += a2*wv; accH[3][j] += a3*wv;
                    }
                }
            }
        }
        __syncthreads();   // all FMA reads of state done before state update

        #pragma unroll
        for (int i = 0; i < 4; ++i) {
            const int m = my*4 + i;
            const int seq = seq0 + m;
            #pragma unroll
            for (int j = 0; j < 4; ++j) {
                const int c = ox + 32*j;
                float r  = sigmoidf_(acc[i][j]     + br2[j]);
                float z  = sigmoidf_(acc[i][j + 4] + bz2[j]);
                float nn = tanhf_(acc[i][j + 8] + bin[j] + r * (accH[i][j] + bhn[j]));
                float hv = Xs[m*G3 + 256 + c];
                hv = (1.f - z)*nn + z*hv;
                Xs[m*G3 + 256 + c] = hv;
                if (t < 7) g_yseq[(size_t)(t*BB + seq)*HH + c] = hv;
                else       out[(size_t)seq*HH + c] = hv;     // hT
            }
        }
    }
}

// ---------------- loss: y_hat for sampled nodes + partial sums ---------------
__global__ void loss_kernel(const float* __restrict__ y0,
                            const int* __restrict__ walks,
                            const int* __restrict__ idxs,
                            const float* __restrict__ b_ss)
{
    const int bid = blockIdx.x;              // 0..2799
    const int s   = bid / (SUBN*7);
    const int rem = bid % (SUBN*7);
    const int i   = rem / 7;
    const int tt  = rem % 7;
    const int node = idxs[i];
    const int seq  = s*NN + node;
    __shared__ float yv[128];
    const int tid = threadIdx.x;             // 64 threads
    yv[tid]      = g_yseq[(size_t)(tt*BB + seq)*HH + tid];
    yv[tid + 64] = g_yseq[(size_t)(tt*BB + seq)*HH + tid + 64];
    __syncthreads();

    float acc = b_ss[tid];
    #pragma unroll 8
    for (int k = 0; k < 128; ++k) acc += g_Wsst[k*ORIG_ + tid] * yv[k];

    const int wnode = walks[(size_t)seq*LL + 6 - tt];   // walks_f[tt+1]
    const float yt = y0[(size_t)wnode*ORIG_ + tid];
    const float spP = fmaxf(acc, 0.f) + log1pf(expf(-fabsf(acc)));  // softplus(acc)
    const float spN = spP - acc;                                    // softplus(-acc)
    float ta = yt * spN;
    float tb = (1.f - yt) * spP;
    float ty = yt;

    #pragma unroll
    for (int off = 16; off; off >>= 1) {
        ta += __shfl_down_sync(0xffffffffu, ta, off);
        tb += __shfl_down_sync(0xffffffffu, tb, off);
        ty += __shfl_down_sync(0xffffffffu, ty, off);
    }
    __shared__ float rA[2], rB[2], rY[2];
    if ((tid & 31) == 0) { rA[tid >> 5] = ta; rB[tid >> 5] = tb; rY[tid >> 5] = ty; }
    __syncthreads();
    if (tid == 0) {
        g_partA[bid] = rA[0] + rA[1];
        g_partB[bid] = rB[0] + rB[1];
        g_partY[bid] = rY[0] + rY[1];
    }
}

__global__ void finalize_kernel(float* __restrict__ out, int out_size)
{
    __shared__ float sA[256], sB[256], sY[256];
    const int tid = threadIdx.x;
    float a = 0.f, b = 0.f, y = 0.f;
    for (int i = tid; i < LOSS_BLOCKS; i += 256) {
        a += g_partA[i]; b += g_partB[i]; y += g_partY[i];
    }
    sA[tid] = a; sB[tid] = b; sY[tid] = y;
    __syncthreads();
    for (int off = 128; off; off >>= 1) {
        if (tid < off) { sA[tid] += sA[tid+off]; sB[tid] += sB[tid+off]; sY[tid] += sY[tid+off]; }
        __syncthreads();
    }
    if (tid == 0) out[out_size - 1] = sA[0] / sY[0] + sB[0] / (float)CNT;
}

// ---------------- launch -----------------------------------------------------
extern "C" void kernel_launch(void* const* d_in, const int* in_sizes, int n_in,
                              void* d_out, int out_size)
{
    const float* h_    = (const float*)d_in[0];
    const float* y0    = (const float*)d_in[1];
    const float* Wih_w = (const float*)d_in[2];
    const float* Whh_w = (const float*)d_in[3];
    const float* bih_w = (const float*)d_in[4];
    const float* bhh_w = (const float*)d_in[5];
    const float* Wih   = (const float*)d_in[6];
    const float* Whh   = (const float*)d_in[7];
    const float* bih   = (const float*)d_in[8];
    const float* bhh   = (const float*)d_in[9];
    const float* W_ss  = (const float*)d_in[10];
    const float* b_ss  = (const float*)d_in[11];
    const int*   walks = (const int*)d_in[12];
    const int*   idxs  = (const int*)d_in[13];
    float* out = (float*)d_out;
    (void)in_sizes; (void)n_in;

    cudaFuncSetAttribute(walk_gru_kernel, cudaFuncAttributeMaxDynamicSharedMemorySize, SMEM1);
    cudaFuncSetAttribute(main_gru_kernel, cudaFuncAttributeMaxDynamicSharedMemorySize, SMEM2);

    prep_kernel<<<(G3*G3 + 255)/256, 256>>>(Wih_w, bih_w, Whh_w, Wih, Whh, W_ss);
    walk_gru_kernel<<<BB/32, 256, SMEM1>>>(walks, bhh_w);
    main_gru_kernel<<<BB/32, 256, SMEM2>>>(walks, h_, bih, bhh, out);
    loss_kernel<<<LOSS_BLOCKS, 64>>>(y0, walks, idxs, b_ss);
    finalize_kernel<<<1, 256>>>(out, out_size);
}

// round 2
// speedup vs baseline: 1.2308x; 1.2308x over previous
#include <cuda_runtime.h>
#include <math.h>

#define NN    10000
#define SS_   4
#define LL    8
#define BB    (SS_*NN)          // 40000 sequences
#define HH    128
#define G3    384               // 3*H
#define ORIG_ 64
#define SUBN  100
#define LOSS_BLOCKS (SS_*SUBN*(LL-1))   // 2800
#define CNT   (SS_*SUBN*(LL-1)*ORIG_)   // 179200

typedef unsigned long long ull;

// ---------------- device scratch ---------------------------------------------
__device__ float g_T[LL*G3];            // one-hot input table: T[u][o] = Wih_w[o][u]+bih_w[o]
__device__ float g_W1t[HH*G3];          // Whh_w transposed [k][o]
__device__ float g_W2t[G3*G3];          // [Wih | Whh] transposed [k][o]
__device__ float g_Wsst[HH*ORIG_];      // W_ss transposed [k][o]
__device__ float g_ywalk[(size_t)LL*BB*HH];
__device__ float g_yseq[(size_t)(LL-1)*BB*HH];
__device__ float g_partA[LOSS_BLOCKS];
__device__ float g_partB[LOSS_BLOCKS];
__device__ float g_partY[LOSS_BLOCKS];

// ---------------- f32x2 helpers ----------------------------------------------
__device__ __forceinline__ void ffma2(ull& acc, ull a, ull b) {
    asm("fma.rn.f32x2 %0, %1, %2, %0;" : "+l"(acc) : "l"(a), "l"(b));
}
__device__ __forceinline__ ull pack2(float x, float y) {
    ull r; asm("mov.b64 %0, {%1, %2};" : "=l"(r) : "f"(x), "f"(y)); return r;
}
__device__ __forceinline__ void unpack2(ull v, float& lo, float& hi) {
    asm("mov.b64 {%0, %1}, %2;" : "=f"(lo), "=f"(hi) : "l"(v));
}

// ---------------- activations (accurate fp32) --------------------------------
__device__ __forceinline__ float sigmoidf_(float x) {
    return __fdividef(1.f, 1.f + __expf(-x));
}
__device__ __forceinline__ float tanhf_(float x) {
    return 1.f - 2.f * __fdividef(1.f, __expf(2.f * x) + 1.f);
}

// ---------------- prep -------------------------------------------------------
__global__ void prep_kernel(const float* __restrict__ Wih_w, const float* __restrict__ bih_w,
                            const float* __restrict__ Whh_w, const float* __restrict__ Wih,
                            const float* __restrict__ Whh,   const float* __restrict__ W_ss)
{
    int i = blockIdx.x * blockDim.x + threadIdx.x;
    if (i < LL*G3)  { int u = i / G3, o = i % G3; g_T[i]   = Wih_w[o*LL + u] + bih_w[o]; }
    if (i < HH*G3)  { int k = i / G3, o = i % G3; g_W1t[i] = Whh_w[o*HH + k]; }
    if (i < G3*G3)  { int k = i / G3, o = i % G3;
                      g_W2t[i] = (k < 256) ? Wih[o*256 + k] : Whh[o*HH + (k - 256)]; }
    if (i < HH*ORIG_){ int k = i / ORIG_, o = i % ORIG_; g_Wsst[i] = W_ss[o*HH + k]; }
}

// ---------------- phase 1: walk GRU ------------------------------------------
// block: 32 sequences, 256 threads. warp my owns rows m=4my..4my+3 (private).
// thread owns outputs c = 4*ox + 128*gate (4 consecutive per gate) -> LDS.128 weights.
#define SMEM1 ((32*128 + 32*384)*4 + 32*8*4)
__global__ void __launch_bounds__(256) walk_gru_kernel(
    const int* __restrict__ walks, const float* __restrict__ bhh_w)
{
    extern __shared__ float sm[];
    float* Hs = sm;                 // 32*128 state
    float* Ws = sm + 32*128;        // 32*384 weight chunk
    int*   U  = (int*)(Ws + 32*384);
    const int tid  = threadIdx.x;
    const int ox   = tid & 31;
    const int my   = tid >> 5;
    const int my4  = my * 4;
    const int c0   = ox << 2;       // base output channel within gate
    const int seq0 = blockIdx.x * 32;

    for (int q = tid; q < 32*128; q += 256) Hs[q] = 0.f;

    { // uniqueness: U[m][t] = first occurrence index of walks[7-t]
        int m = tid >> 3, t = tid & 7;
        const int* w = walks + (size_t)(seq0 + m) * LL;
        int tgt = w[7 - t];
        int u = 0;
        #pragma unroll
        for (int j = 7; j >= 0; --j) if (w[j] == tgt) u = j;
        U[m*8 + t] = u;
    }

    const float4 br = *(const float4*)(bhh_w + c0);
    const float4 bz = *(const float4*)(bhh_w + 128 + c0);
    const float4 bn = *(const float4*)(bhh_w + 256 + c0);
    __syncthreads();

    for (int t = 0; t < LL; ++t) {
        ull aR[4][2], aZ[4][2], aN[4][2];
        #pragma unroll
        for (int i = 0; i < 4; ++i) {
            aR[i][0]=aR[i][1]=0ull; aZ[i][0]=aZ[i][1]=0ull; aN[i][0]=aN[i][1]=0ull;
        }

        for (int kc = 0; kc < 4; ++kc) {
            __syncthreads();
            const float4* src = (const float4*)(g_W1t + kc*(32*G3));
            float4* dst = (float4*)Ws;
            #pragma unroll
            for (int q = 0; q < 12; ++q) dst[tid + 256*q] = src[tid + 256*q];
            __syncthreads();
            const int kbase = kc*32;
            #pragma unroll 2
            for (int kk = 0; kk < 32; ++kk) {
                const int k = kbase + kk;
                ull d0 = pack2(Hs[(my4+0)*128 + k], Hs[(my4+0)*128 + k]);
                ull d1 = pack2(Hs[(my4+1)*128 + k], Hs[(my4+1)*128 + k]);
                ull d2 = pack2(Hs[(my4+2)*128 + k], Hs[(my4+2)*128 + k]);
                ull d3 = pack2(Hs[(my4+3)*128 + k], Hs[(my4+3)*128 + k]);
                const float* wp = Ws + kk*G3 + c0;
                const ulonglong2 wR = *(const ulonglong2*)wp;
                const ulonglong2 wZ = *(const ulonglong2*)(wp + 128);
                const ulonglong2 wN = *(const ulonglong2*)(wp + 256);
                ffma2(aR[0][0], d0, wR.x); ffma2(aR[0][1], d0, wR.y);
                ffma2(aR[1][0], d1, wR.x); ffma2(aR[1][1], d1, wR.y);
                ffma2(aR[2][0], d2, wR.x); ffma2(aR[2][1], d2, wR.y);
                ffma2(aR[3][0], d3, wR.x); ffma2(aR[3][1], d3, wR.y);
                ffma2(aZ[0][0], d0, wZ.x); ffma2(aZ[0][1], d0, wZ.y);
                ffma2(aZ[1][0], d1, wZ.x); ffma2(aZ[1][1], d1, wZ.y);
                ffma2(aZ[2][0], d2, wZ.x); ffma2(aZ[2][1], d2, wZ.y);
                ffma2(aZ[3][0], d3, wZ.x); ffma2(aZ[3][1], d3, wZ.y);
                ffma2(aN[0][0], d0, wN.x); ffma2(aN[0][1], d0, wN.y);
                ffma2(aN[1][0], d1, wN.x); ffma2(aN[1][1], d1, wN.y);
                ffma2(aN[2][0], d2, wN.x); ffma2(aN[2][1], d2, wN.y);
                ffma2(aN[3][0], d3, wN.x); ffma2(aN[3][1], d3, wN.y);
            }
        }

        // state update: warp-private rows, no sync needed
        #pragma unroll
        for (int i = 0; i < 4; ++i) {
            const int m = my4 + i;
            const int seq = seq0 + m;
            const float* Tp = g_T + U[m*8 + t]*G3;
            const float4 tR = *(const float4*)(Tp + c0);
            const float4 tZ = *(const float4*)(Tp + 128 + c0);
            const float4 tN = *(const float4*)(Tp + 256 + c0);
            float R[4], Z[4], Nh[4];
            unpack2(aR[i][0], R[0], R[1]);  unpack2(aR[i][1], R[2], R[3]);
            unpack2(aZ[i][0], Z[0], Z[1]);  unpack2(aZ[i][1], Z[2], Z[3]);
            unpack2(aN[i][0], Nh[0], Nh[1]); unpack2(aN[i][1], Nh[2], Nh[3]);
            float4 hOld = *(const float4*)(Hs + m*128 + c0);
            float4 hNew;
            {
                float r  = sigmoidf_(R[0] + br.x + tR.x);
                float z  = sigmoidf_(Z[0] + bz.x + tZ.x);
                float nn = tanhf_(tN.x + r * (Nh[0] + bn.x));
                hNew.x = (1.f - z)*nn + z*hOld.x;
            }{
                float r  = sigmoidf_(R[1] + br.y + tR.y);
                float z  = sigmoidf_(Z[1] + bz.y + tZ.y);
                float nn = tanhf_(tN.y + r * (Nh[1] + bn.y));
                hNew.y = (1.f - z)*nn + z*hOld.y;
            }{
                float r  = sigmoidf_(R[2] + br.z + tR.z);
                float z  = sigmoidf_(Z[2] + bz.z + tZ.z);
                float nn = tanhf_(tN.z + r * (Nh[2] + bn.z));
                hNew.z = (1.f - z)*nn + z*hOld.z;
            }{
                float r  = sigmoidf_(R[3] + br.w + tR.w);
                float z  = sigmoidf_(Z[3] + bz.w + tZ.w);
                float nn = tanhf_(tN.w + r * (Nh[3] + bn.w));
                hNew.w = (1.f - z)*nn + z*hOld.w;
            }
            *(float4*)(Hs + m*128 + c0) = hNew;
            *(float4*)(g_ywalk + (size_t)(t*BB + seq)*HH + c0) = hNew;
        }
    }
}

// ---------------- phase 2: main GRU ------------------------------------------
// x_cat = [ h[walks_f[t]] (128) | y_walk[t] (128) | state (128) ]
#define SMEM2 ((32*384*2)*4 + 32*8*4)
__global__ void __launch_bounds__(256) main_gru_kernel(
    const int* __restrict__ walks, const float* __restrict__ hfeat,
    const float* __restrict__ bih, const float* __restrict__ bhh,
    float* __restrict__ out)
{
    extern __shared__ float sm[];
    float* Xs = sm;                  // 32*384
    float* Ws = sm + 32*384;         // 32*384
    int*   wk = (int*)(Ws + 32*384);
    const int tid  = threadIdx.x;
    const int ox   = tid & 31;
    const int my   = tid >> 5;
    const int my4  = my * 4;
    const int c0   = ox << 2;
    const int seq0 = blockIdx.x * 32;

    { int m = tid >> 3, j = tid & 7; wk[m*8 + j] = walks[(size_t)(seq0 + m)*LL + j]; }

    // h0 = h_walk = y_walk[7]
    for (int q = tid; q < 32*32; q += 256) {
        int m = q >> 5, c4 = q & 31;
        ((float4*)(Xs + m*G3 + 256))[c4] =
            ((const float4*)(g_ywalk + (size_t)(7*BB + seq0 + m)*HH))[c4];
    }
    float4 br2, bz2, bin, bhn;
    {
        const float4 i0 = *(const float4*)(bih + c0);
        const float4 h0 = *(const float4*)(bhh + c0);
        const float4 i1 = *(const float4*)(bih + 128 + c0);
        const float4 h1 = *(const float4*)(bhh + 128 + c0);
        br2 = make_float4(i0.x+h0.x, i0.y+h0.y, i0.z+h0.z, i0.w+h0.w);
        bz2 = make_float4(i1.x+h1.x, i1.y+h1.y, i1.z+h1.z, i1.w+h1.w);
        bin = *(const float4*)(bih + 256 + c0);
        bhn = *(const float4*)(bhh + 256 + c0);
    }

    for (int t = 0; t < LL; ++t) {
        __syncthreads();   // all prior-step reads of Xs input region done
        for (int q = tid; q < 32*32; q += 256) {
            int m = q >> 5, c4 = q & 31;
            int node = wk[m*8 + 7 - t];
            ((float4*)(Xs + m*G3))[c4] = ((const float4*)(hfeat + (size_t)node*HH))[c4];
            ((float4*)(Xs + m*G3 + 128))[c4] =
                ((const float4*)(g_ywalk + (size_t)(t*BB + seq0 + m)*HH))[c4];
        }

        ull aR[4][2], aZ[4][2], aN[4][2], aH[4][2];
        #pragma unroll
        for (int i = 0; i < 4; ++i) {
            aR[i][0]=aR[i][1]=0ull; aZ[i][0]=aZ[i][1]=0ull;
            aN[i][0]=aN[i][1]=0ull; aH[i][0]=aH[i][1]=0ull;
        }

        for (int kc = 0; kc < 12; ++kc) {
            __syncthreads();
            const float4* src = (const float4*)(g_W2t + kc*(32*G3));
            float4* dst = (float4*)Ws;
            #pragma unroll
            for (int q = 0; q < 12; ++q) dst[tid + 256*q] = src[tid + 256*q];
            __syncthreads();
            const int kbase = kc*32;
            if (kc < 8) {   // input part: n-channel sums -> aN
                #pragma unroll 2
                for (int kk = 0; kk < 32; ++kk) {
                    const int k = kbase + kk;
                    ull d0 = pack2(Xs[(my4+0)*G3 + k], Xs[(my4+0)*G3 + k]);
                    ull d1 = pack2(Xs[(my4+1)*G3 + k], Xs[(my4+1)*G3 + k]);
                    ull d2 = pack2(Xs[(my4+2)*G3 + k], Xs[(my4+2)*G3 + k]);
                    ull d3 = pack2(Xs[(my4+3)*G3 + k], Xs[(my4+3)*G3 + k]);
                    const float* wp = Ws + kk*G3 + c0;
                    const ulonglong2 wR = *(const ulonglong2*)wp;
                    const ulonglong2 wZ = *(const ulonglong2*)(wp + 128);
                    const ulonglong2 wN = *(const ulonglong2*)(wp + 256);
                    ffma2(aR[0][0], d0, wR.x); ffma2(aR[0][1], d0, wR.y);
                    ffma2(aR[1][0], d1, wR.x); ffma2(aR[1][1], d1, wR.y);
                    ffma2(aR[2][0], d2, wR.x); ffma2(aR[2][1], d2, wR.y);
                    ffma2(aR[3][0], d3, wR.x); ffma2(aR[3][1], d3, wR.y);
                    ffma2(aZ[0][0], d0, wZ.x); ffma2(aZ[0][1], d0, wZ.y);
                    ffma2(aZ[1][0], d1, wZ.x); ffma2(aZ[1][1], d1, wZ.y);
                    ffma2(aZ[2][0], d2, wZ.x); ffma2(aZ[2][1], d2, wZ.y);
                    ffma2(aZ[3][0], d3, wZ.x); ffma2(aZ[3][1], d3, wZ.y);
                    ffma2(aN[0][0], d0, wN.x); ffma2(aN[0][1], d0, wN.y);
                    ffma2(aN[1][0], d1, wN.x); ffma2(aN[1][1], d1, wN.y);
                    ffma2(aN[2][0], d2, wN.x); ffma2(aN[2][1], d2, wN.y);
                    ffma2(aN[3][0], d3, wN.x); ffma2(aN[3][1], d3, wN.y);
                }
            } else {        // hidden part: n-channel sums -> aH (multiplied by r later)
                #pragma unroll 2
                for (int kk = 0; kk < 32; ++kk) {
                    const int k = kbase + kk;
                    ull d0 = pack2(Xs[(my4+0)*G3 + k], Xs[(my4+0)*G3 + k]);
                    ull d1 = pack2(Xs[(my4+1)*G3 + k], Xs[(my4+1)*G3 + k]);
                    ull d2 = pack2(Xs[(my4+2)*G3 + k], Xs[(my4+2)*G3 + k]);
                    ull d3 = pack2(Xs[(my4+3)*G3 + k], Xs[(my4+3)*G3 + k]);
                    const float* wp = Ws + kk*G3 + c0;
                    const ulonglong2 wR = *(const ulonglong2*)wp;
                    const ulonglong2 wZ = *(const ulonglong2*)(wp + 128);
                    const ulonglong2 wN = *(const ulonglong2*)(wp + 256);
                    ffma2(aR[0][0], d0, wR.x); ffma2(aR[0][1], d0, wR.y);
                    ffma2(aR[1][0], d1, wR.x); ffma2(aR[1][1], d1, wR.y);
                    ffma2(aR[2][0], d2, wR.x); ffma2(aR[2][1], d2, wR.y);
                    ffma2(aR[3][0], d3, wR.x); ffma2(aR[3][1], d3, wR.y);
                    ffma2(aZ[0][0], d0, wZ.x); ffma2(aZ[0][1], d0, wZ.y);
                    ffma2(aZ[1][0], d1, wZ.x); ffma2(aZ[1][1], d1, wZ.y);
                    ffma2(aZ[2][0], d2, wZ.x); ffma2(aZ[2][1], d2, wZ.y);
                    ffma2(aZ[3][0], d3, wZ.x); ffma2(aZ[3][1], d3, wZ.y);
                    ffma2(aH[0][0], d0, wN.x); ffma2(aH[0][1], d0, wN.y);
                    ffma2(aH[1][0], d1, wN.x); ffma2(aH[1][1], d1, wN.y);
                    ffma2(aH[2][0], d2, wN.x); ffma2(aH[2][1], d2, wN.y);
                    ffma2(aH[3][0], d3, wN.x); ffma2(aH[3][1], d3, wN.y);
                }
            }
        }

        // state update: warp-private rows
        #pragma unroll
        for (int i = 0; i < 4; ++i) {
            const int m = my4 + i;
            const int seq = seq0 + m;
            float R[4], Z[4], Ni[4], Nh[4];
            unpack2(aR[i][0], R[0], R[1]);   unpack2(aR[i][1], R[2], R[3]);
            unpack2(aZ[i][0], Z[0], Z[1]);   unpack2(aZ[i][1], Z[2], Z[3]);
            unpack2(aN[i][0], Ni[0], Ni[1]); unpack2(aN[i][1], Ni[2], Ni[3]);
            unpack2(aH[i][0], Nh[0], Nh[1]); unpack2(aH[i][1], Nh[2], Nh[3]);
            float4 hOld = *(const float4*)(Xs + m*G3 + 256 + c0);
            float4 hNew;
            {
                float r  = sigmoidf_(R[0] + br2.x);
                float z  = sigmoidf_(Z[0] + bz2.x);
                float nn = tanhf_(Ni[0] + bin.x + r * (Nh[0] + bhn.x));
                hNew.x = (1.f - z)*nn + z*hOld.x;
            }{
                float r  = sigmoidf_(R[1] + br2.y);
                float z  = sigmoidf_(Z[1] + bz2.y);
                float nn = tanhf_(Ni[1] + bin.y + r * (Nh[1] + bhn.y));
                hNew.y = (1.f - z)*nn + z*hOld.y;
            }{
                float r  = sigmoidf_(R[2] + br2.z);
                float z  = sigmoidf_(Z[2] + bz2.z);
                float nn = tanhf_(Ni[2] + bin.z + r * (Nh[2] + bhn.z));
                hNew.z = (1.f - z)*nn + z*hOld.z;
            }{
                float r  = sigmoidf_(R[3] + br2.w);
                float z  = sigmoidf_(Z[3] + bz2.w);
                float nn = tanhf_(Ni[3] + bin.w + r * (Nh[3] + bhn.w));
                hNew.w = (1.f - z)*nn + z*hOld.w;
            }
            *(float4*)(Xs + m*G3 + 256 + c0) = hNew;
            if (t < 7) *(float4*)(g_yseq + (size_t)(t*BB + seq)*HH + c0) = hNew;
            else       *(float4*)(out + (size_t)seq*HH + c0) = hNew;
        }
    }
}

// ---------------- loss -------------------------------------------------------
__global__ void loss_kernel(const float* __restrict__ y0,
                            const int* __restrict__ walks,
                            const int* __restrict__ idxs,
                            const float* __restrict__ b_ss)
{
    const int bid = blockIdx.x;
    const int s   = bid / (SUBN*7);
    const int rem = bid % (SUBN*7);
    const int i   = rem / 7;
    const int tt  = rem % 7;
    const int node = idxs[i];
    const int seq  = s*NN + node;
    __shared__ float yv[128];
    const int tid = threadIdx.x;             // 64 threads
    yv[tid]      = g_yseq[(size_t)(tt*BB + seq)*HH + tid];
    yv[tid + 64] = g_yseq[(size_t)(tt*BB + seq)*HH + tid + 64];
    __syncthreads();

    float acc = b_ss[tid];
    #pragma unroll 8
    for (int k = 0; k < 128; ++k) acc += g_Wsst[k*ORIG_ + tid] * yv[k];

    const int wnode = walks[(size_t)seq*LL + 6 - tt];
    const float yt = y0[(size_t)wnode*ORIG_ + tid];
    const float spP = fmaxf(acc, 0.f) + log1pf(expf(-fabsf(acc)));
    const float spN = spP - acc;
    float ta = yt * spN;
    float tb = (1.f - yt) * spP;
    float ty = yt;

    #pragma unroll
    for (int off = 16; off; off >>= 1) {
        ta += __shfl_down_sync(0xffffffffu, ta, off);
        tb += __shfl_down_sync(0xffffffffu, tb, off);
        ty += __shfl_down_sync(0xffffffffu, ty, off);
    }
    __shared__ float rA[2], rB[2], rY[2];
    if ((tid & 31) == 0) { rA[tid >> 5] = ta; rB[tid >> 5] = tb; rY[tid >> 5] = ty; }
    __syncthreads();
    if (tid == 0) {
        g_partA[bid] = rA[0] + rA[1];
        g_partB[bid] = rB[0] + rB[1];
        g_partY[bid] = rY[0] + rY[1];
    }
}

__global__ void finalize_kernel(float* __restrict__ out, int out_size)
{
    __shared__ float sA[256], sB[256], sY[256];
    const int tid = threadIdx.x;
    float a = 0.f, b = 0.f, y = 0.f;
    for (int i = tid; i < LOSS_BLOCKS; i += 256) {
        a += g_partA[i]; b += g_partB[i]; y += g_partY[i];
    }
    sA[tid] = a; sB[tid] = b; sY[tid] = y;
    __syncthreads();
    for (int off = 128; off; off >>= 1) {
        if (tid < off) { sA[tid] += sA[tid+off]; sB[tid] += sB[tid+off]; sY[tid] += sY[tid+off]; }
        __syncthreads();
    }
    if (tid == 0) out[out_size - 1] = sA[0] / sY[0] + sB[0] / (float)CNT;
}

// ---------------- launch -----------------------------------------------------
extern "C" void kernel_launch(void* const* d_in, const int* in_sizes, int n_in,
                              void* d_out, int out_size)
{
    const float* h_    = (const float*)d_in[0];
    const float* y0    = (const float*)d_in[1];
    const float* Wih_w = (const float*)d_in[2];
    const float* Whh_w = (const float*)d_in[3];
    const float* bih_w = (const float*)d_in[4];
    const float* bhh_w = (const float*)d_in[5];
    const float* Wih   = (const float*)d_in[6];
    const float* Whh   = (const float*)d_in[7];
    const float* bih   = (const float*)d_in[8];
    const float* bhh   = (const float*)d_in[9];
    const float* W_ss  = (const float*)d_in[10];
    const float* b_ss  = (const float*)d_in[11];
    const int*   walks = (const int*)d_in[12];
    const int*   idxs  = (const int*)d_in[13];
    float* out = (float*)d_out;
    (void)in_sizes; (void)n_in;

    cudaFuncSetAttribute(walk_gru_kernel, cudaFuncAttributeMaxDynamicSharedMemorySize, SMEM1);
    cudaFuncSetAttribute(main_gru_kernel, cudaFuncAttributeMaxDynamicSharedMemorySize, SMEM2);

    prep_kernel<<<(G3*G3 + 255)/256, 256>>>(Wih_w, bih_w, Whh_w, Wih, Whh, W_ss);
    walk_gru_kernel<<<BB/32, 256, SMEM1>>>(walks, bhh_w);
    main_gru_kernel<<<BB/32, 256, SMEM2>>>(walks, h_, bih, bhh, out);
    loss_kernel<<<LOSS_BLOCKS, 64>>>(y0, walks, idxs, b_ss);
    finalize_kernel<<<1, 256>>>(out, out_size);
}

// round 6
// speedup vs baseline: 1.5000x; 1.2188x over previous
#include <cuda_runtime.h>
#include <math.h>

#define NN    10000
#define SS_   4
#define LL    8
#define BB    (SS_*NN)          // 40000 sequences
#define HH    128
#define G3    384               // 3*H
#define ORIG_ 64
#define SUBN  100
#define LOSS_BLOCKS (SS_*SUBN*(LL-1))   // 2800
#define CNT   (SS_*SUBN*(LL-1)*ORIG_)   // 179200

typedef unsigned long long ull;

// ---------------- device scratch ---------------------------------------------
__device__ float g_T[LL*G3];            // one-hot table: T[u][o] = Wih_w[o][u]+bih_w[o]
__device__ float g_W1t[HH*G3];          // Whh_w transposed [k][o]
__device__ float g_W2t[G3*G3];          // [Wih | Whh] transposed [k][o]
__device__ float g_Wsst[HH*ORIG_];      // W_ss transposed [k][o]
__device__ float g_ywalk[(size_t)LL*BB*HH];
__device__ float g_yseq[(size_t)(LL-1)*BB*HH];
__device__ float g_partA[LOSS_BLOCKS];
__device__ float g_partB[LOSS_BLOCKS];
__device__ float g_partY[LOSS_BLOCKS];

// ---------------- helpers ----------------------------------------------------
__device__ __forceinline__ void ffma2(ull& acc, ull a, ull b) {
    asm("fma.rn.f32x2 %0, %1, %2, %0;" : "+l"(acc) : "l"(a), "l"(b));
}
__device__ __forceinline__ ull pack2(float x, float y) {
    ull r; asm("mov.b64 %0, {%1, %2};" : "=l"(r) : "f"(x), "f"(y)); return r;
}
__device__ __forceinline__ void unpack2(ull v, float& lo, float& hi) {
    asm("mov.b64 {%0, %1}, %2;" : "=f"(lo), "=f"(hi) : "l"(v));
}
__device__ __forceinline__ void cp_async16(float* sdst, const float* gsrc) {
    unsigned s = (unsigned)__cvta_generic_to_shared(sdst);
    asm volatile("cp.async.cg.shared.global [%0], [%1], 16;" :: "r"(s), "l"(gsrc));
}
#define CP_COMMIT() asm volatile("cp.async.commit_group;" ::)
#define CP_WAIT0()  asm volatile("cp.async.wait_group 0;" ::)

__device__ __forceinline__ float sigmoidf_(float x) {
    return __fdividef(1.f, 1.f + __expf(-x));
}
__device__ __forceinline__ float tanhf_(float x) {
    return 1.f - 2.f * __fdividef(1.f, __expf(2.f * x) + 1.f);
}

// ---------------- prep -------------------------------------------------------
__global__ void prep_kernel(const float* __restrict__ Wih_w, const float* __restrict__ bih_w,
                            const float* __restrict__ Whh_w, const float* __restrict__ Wih,
                            const float* __restrict__ Whh,   const float* __restrict__ W_ss)
{
    int i = blockIdx.x * blockDim.x + threadIdx.x;
    if (i < LL*G3)  { int u = i / G3, o = i % G3; g_T[i]   = Wih_w[o*LL + u] + bih_w[o]; }
    if (i < HH*G3)  { int k = i / G3, o = i % G3; g_W1t[i] = Whh_w[o*HH + k]; }
    if (i < G3*G3)  { int k = i / G3, o = i % G3;
                      g_W2t[i] = (k < 256) ? Wih[o*256 + k] : Whh[o*HH + (k - 256)]; }
    if (i < HH*ORIG_){ int k = i / ORIG_, o = i % ORIG_; g_Wsst[i] = W_ss[o*HH + k]; }
}

// ---------------- phase 1: walk GRU (weights fully resident) -----------------
// 64 rows/block, 512 threads, 1 block/SM. warp my owns rows 4my..4my+3 (private):
// NO syncthreads inside the time loop, NO per-step staging.
#define SMEM1B ((128*G3 + 64*128)*4 + 64*8*4)   // 231,424 B
__global__ void __launch_bounds__(512) walk_gru_kernel(
    const int* __restrict__ walks, const float* __restrict__ bhh_w)
{
    extern __shared__ float sm[];
    float* Ws = sm;                   // 128*384 resident weights
    float* Hs = sm + 128*G3;          // 64*128 state
    int*   U  = (int*)(Hs + 64*128);  // 64*8
    const int tid  = threadIdx.x;
    const int ox   = tid & 31;
    const int my   = tid >> 5;
    const int my4  = my * 4;
    const int c0   = ox << 2;
    const int seq0 = blockIdx.x * 64;

    { // one-time weight load (192 KB)
        const float4* src = (const float4*)g_W1t;
        float4* dst = (float4*)Ws;
        #pragma unroll
        for (int q0 = 0; q0 < 24; ++q0) dst[tid + 512*q0] = src[tid + 512*q0];
    }
    for (int q = tid; q < 64*128; q += 512) Hs[q] = 0.f;
    { // uniqueness: U[m][t] = first occurrence index of walks[7-t]
        int m = tid >> 3, t = tid & 7;
        const int* w = walks + (size_t)(seq0 + m) * LL;
        int tgt = w[7 - t];
        int u = 0;
        #pragma unroll
        for (int j = 7; j >= 0; --j) if (w[j] == tgt) u = j;
        U[m*8 + t] = u;
    }
    __syncthreads();

    const float* xr0 = Hs + (my4+0)*128;
    const float* xr1 = Hs + (my4+1)*128;
    const float* xr2 = Hs + (my4+2)*128;
    const float* xr3 = Hs + (my4+3)*128;

    for (int t = 0; t < LL; ++t) {
        ull aR[4][2], aZ[4][2], aN[4][2];
        #pragma unroll
        for (int i = 0; i < 4; ++i) {
            aR[i][0]=aR[i][1]=0ull; aZ[i][0]=aZ[i][1]=0ull; aN[i][0]=aN[i][1]=0ull;
        }

        #pragma unroll 2
        for (int k4 = 0; k4 < 128; k4 += 4) {
            const float4 A0 = *(const float4*)(xr0 + k4);
            const float4 A1 = *(const float4*)(xr1 + k4);
            const float4 A2 = *(const float4*)(xr2 + k4);
            const float4 A3 = *(const float4*)(xr3 + k4);
            #pragma unroll
            for (int j = 0; j < 4; ++j) {
                const float s0 = j==0?A0.x : j==1?A0.y : j==2?A0.z : A0.w;
                const float s1 = j==0?A1.x : j==1?A1.y : j==2?A1.z : A1.w;
                const float s2 = j==0?A2.x : j==1?A2.y : j==2?A2.z : A2.w;
                const float s3 = j==0?A3.x : j==1?A3.y : j==2?A3.z : A3.w;
                ull d0 = pack2(s0,s0), d1 = pack2(s1,s1), d2 = pack2(s2,s2), d3 = pack2(s3,s3);
                const float* wp = Ws + (k4+j)*G3 + c0;
                const ulonglong2 wR = *(const ulonglong2*)wp;
                const ulonglong2 wZ = *(const ulonglong2*)(wp + 128);
                const ulonglong2 wN = *(const ulonglong2*)(wp + 256);
                ffma2(aR[0][0], d0, wR.x); ffma2(aR[0][1], d0, wR.y);
                ffma2(aR[1][0], d1, wR.x); ffma2(aR[1][1], d1, wR.y);
                ffma2(aR[2][0], d2, wR.x); ffma2(aR[2][1], d2, wR.y);
                ffma2(aR[3][0], d3, wR.x); ffma2(aR[3][1], d3, wR.y);
                ffma2(aZ[0][0], d0, wZ.x); ffma2(aZ[0][1], d0, wZ.y);
                ffma2(aZ[1][0], d1, wZ.x); ffma2(aZ[1][1], d1, wZ.y);
                ffma2(aZ[2][0], d2, wZ.x); ffma2(aZ[2][1], d2, wZ.y);
                ffma2(aZ[3][0], d3, wZ.x); ffma2(aZ[3][1], d3, wZ.y);
                ffma2(aN[0][0], d0, wN.x); ffma2(aN[0][1], d0, wN.y);
                ffma2(aN[1][0], d1, wN.x); ffma2(aN[1][1], d1, wN.y);
                ffma2(aN[2][0], d2, wN.x); ffma2(aN[2][1], d2, wN.y);
                ffma2(aN[3][0], d3, wN.x); ffma2(aN[3][1], d3, wN.y);
            }
        }

        const float4 br = *(const float4*)(bhh_w + c0);
        const float4 bz = *(const float4*)(bhh_w + 128 + c0);
        const float4 bn = *(const float4*)(bhh_w + 256 + c0);
        #pragma unroll
        for (int i = 0; i < 4; ++i) {
            const int m = my4 + i;
            const int seq = seq0 + m;
            const float* Tp = g_T + U[m*8 + t]*G3;
            const float4 tR = *(const float4*)(Tp + c0);
            const float4 tZ = *(const float4*)(Tp + 128 + c0);
            const float4 tN = *(const float4*)(Tp + 256 + c0);
            float R[4], Z[4], Nh[4];
            unpack2(aR[i][0], R[0], R[1]);   unpack2(aR[i][1], R[2], R[3]);
            unpack2(aZ[i][0], Z[0], Z[1]);   unpack2(aZ[i][1], Z[2], Z[3]);
            unpack2(aN[i][0], Nh[0], Nh[1]); unpack2(aN[i][1], Nh[2], Nh[3]);
            float4 hOld = *(const float4*)(Hs + m*128 + c0);
            float4 hNew;
            {
                float r = sigmoidf_(R[0] + br.x + tR.x);
                float z = sigmoidf_(Z[0] + bz.x + tZ.x);
                float n = tanhf_(tN.x + r * (Nh[0] + bn.x));
                hNew.x = (1.f - z)*n + z*hOld.x;
            }{
                float r = sigmoidf_(R[1] + br.y + tR.y);
                float z = sigmoidf_(Z[1] + bz.y + tZ.y);
                float n = tanhf_(tN.y + r * (Nh[1] + bn.y));
                hNew.y = (1.f - z)*n + z*hOld.y;
            }{
                float r = sigmoidf_(R[2] + br.z + tR.z);
                float z = sigmoidf_(Z[2] + bz.z + tZ.z);
                float n = tanhf_(tN.z + r * (Nh[2] + bn.z));
                hNew.z = (1.f - z)*n + z*hOld.z;
            }{
                float r = sigmoidf_(R[3] + br.w + tR.w);
                float z = sigmoidf_(Z[3] + bz.w + tZ.w);
                float n = tanhf_(tN.w + r * (Nh[3] + bn.w));
                hNew.w = (1.f - z)*n + z*hOld.w;
            }
            *(float4*)(Hs + m*128 + c0) = hNew;
            *(float4*)(g_ywalk + (size_t)(t*BB + seq)*HH + c0) = hNew;
        }
        // no sync: state rows are warp-private
    }
}

// ---------------- phase 2: main GRU (double-buffered cp.async) ----------------
#define SMEM2B ((64*G3 + 2*32*G3)*4 + 64*8*4)   // 198,656 B

__device__ __forceinline__ void stage_chunk(float* dst, const float* src, int tid) {
    #pragma unroll
    for (int q0 = 0; q0 < 6; ++q0) {
        int idx = tid + 512*q0;     // 3072 float4 = 48 KB
        cp_async16(dst + idx*4, src + idx*4);
    }
}

template<bool HID>
__device__ __forceinline__ void chunk_fma(
    const float* __restrict__ xr0, const float* __restrict__ xr1,
    const float* __restrict__ xr2, const float* __restrict__ xr3,
    const float* __restrict__ Wcur, int kb, int c0,
    ull (&aR)[4][2], ull (&aZ)[4][2], ull (&aN)[4][2], ull (&aH)[4][2])
{
    #pragma unroll 2
    for (int k4 = 0; k4 < 32; k4 += 4) {
        const float4 A0 = *(const float4*)(xr0 + kb + k4);
        const float4 A1 = *(const float4*)(xr1 + kb + k4);
        const float4 A2 = *(const float4*)(xr2 + kb + k4);
        const float4 A3 = *(const float4*)(xr3 + kb + k4);
        #pragma unroll
        for (int j = 0; j < 4; ++j) {
            const float s0 = j==0?A0.x : j==1?A0.y : j==2?A0.z : A0.w;
            const float s1 = j==0?A1.x : j==1?A1.y : j==2?A1.z : A1.w;
            const float s2 = j==0?A2.x : j==1?A2.y : j==2?A2.z : A2.w;
            const float s3 = j==0?A3.x : j==1?A3.y : j==2?A3.z : A3.w;
            ull d0 = pack2(s0,s0), d1 = pack2(s1,s1), d2 = pack2(s2,s2), d3 = pack2(s3,s3);
            const float* wp = Wcur + (k4+j)*G3 + c0;
            const ulonglong2 wR = *(const ulonglong2*)wp;
            const ulonglong2 wZ = *(const ulonglong2*)(wp + 128);
            const ulonglong2 wN = *(const ulonglong2*)(wp + 256);
            ffma2(aR[0][0], d0, wR.x); ffma2(aR[0][1], d0, wR.y);
            ffma2(aR[1][0], d1, wR.x); ffma2(aR[1][1], d1, wR.y);
            ffma2(aR[2][0], d2, wR.x); ffma2(aR[2][1], d2, wR.y);
            ffma2(aR[3][0], d3, wR.x); ffma2(aR[3][1], d3, wR.y);
            ffma2(aZ[0][0], d0, wZ.x); ffma2(aZ[0][1], d0, wZ.y);
            ffma2(aZ[1][0], d1, wZ.x); ffma2(aZ[1][1], d1, wZ.y);
            ffma2(aZ[2][0], d2, wZ.x); ffma2(aZ[2][1], d2, wZ.y);
            ffma2(aZ[3][0], d3, wZ.x); ffma2(aZ[3][1], d3, wZ.y);
            if constexpr (!HID) {
                ffma2(aN[0][0], d0, wN.x); ffma2(aN[0][1], d0, wN.y);
                ffma2(aN[1][0], d1, wN.x); ffma2(aN[1][1], d1, wN.y);
                ffma2(aN[2][0], d2, wN.x); ffma2(aN[2][1], d2, wN.y);
                ffma2(aN[3][0], d3, wN.x); ffma2(aN[3][1], d3, wN.y);
            } else {
                ffma2(aH[0][0], d0, wN.x); ffma2(aH[0][1], d0, wN.y);
                ffma2(aH[1][0], d1, wN.x); ffma2(aH[1][1], d1, wN.y);
                ffma2(aH[2][0], d2, wN.x); ffma2(aH[2][1], d2, wN.y);
                ffma2(aH[3][0], d3, wN.x); ffma2(aH[3][1], d3, wN.y);
            }
        }
    }
}

__global__ void __launch_bounds__(512) main_gru_kernel(
    const int* __restrict__ walks, const float* __restrict__ hfeat,
    const float* __restrict__ bih, const float* __restrict__ bhh,
    float* __restrict__ out)
{
    extern __shared__ float sm[];
    float* Xs = sm;                     // 64*384: [input_h 128 | y_walk 128 | state 128]
    float* W0 = sm + 64*G3;             // 32*384
    float* W1 = W0 + 32*G3;             // 32*384
    int*   wk = (int*)(W1 + 32*G3);     // 64*8
    const int tid  = threadIdx.x;
    const int ox   = tid & 31;
    const int my   = tid >> 5;
    const int my4  = my * 4;
    const int c0   = ox << 2;
    const int seq0 = blockIdx.x * 64;

    { int m = tid >> 3, j = tid & 7; wk[m*8 + j] = walks[(size_t)(seq0 + m)*LL + j]; }
    // h0 = h_walk = y_walk[7]
    for (int q = tid; q < 64*32; q += 512) {
        int m = q >> 5, c4 = q & 31;
        ((float4*)(Xs + m*G3 + 256))[c4] =
            ((const float4*)(g_ywalk + ((size_t)7*BB + seq0 + m)*HH))[c4];
    }
    __syncthreads();      // wk + state visible

    stage_chunk(W0, g_W2t, tid);
    { // Xs fill for t = 0
        #pragma unroll
        for (int q0 = 0; q0 < 4; ++q0) {
            int q = tid + 512*q0;
            int m = q >> 5, c4 = q & 31;
            int node = wk[m*8 + 7];
            cp_async16(Xs + m*G3 + c4*4,       hfeat + (size_t)node*HH + c4*4);
            cp_async16(Xs + m*G3 + 128 + c4*4, g_ywalk + ((size_t)0*BB + seq0 + m)*HH + c4*4);
        }
    }
    CP_COMMIT();

    const float* xr0 = Xs + (my4+0)*G3;
    const float* xr1 = Xs + (my4+1)*G3;
    const float* xr2 = Xs + (my4+2)*G3;
    const float* xr3 = Xs + (my4+3)*G3;

    for (int t = 0; t < LL; ++t) {
        ull aR[4][2], aZ[4][2], aN[4][2], aH[4][2];
        #pragma unroll
        for (int i = 0; i < 4; ++i) {
            aR[i][0]=aR[i][1]=0ull; aZ[i][0]=aZ[i][1]=0ull;
            aN[i][0]=aN[i][1]=0ull; aH[i][0]=aH[i][1]=0ull;
        }

        for (int kc = 0; kc < 12; ++kc) {
            CP_WAIT0();
            __syncthreads();     // current chunk (and fill) visible; old buffer free
            const float* Wcur = (kc & 1) ? W1 : W0;
            if (kc < 11) {
                stage_chunk((kc & 1) ? W0 : W1, g_W2t + (size_t)(kc+1)*32*G3, tid);
                CP_COMMIT();
            } else if (t < 7) {
                stage_chunk(W0, g_W2t, tid);     // chunk 0 for next step
                CP_COMMIT();
            }
            if (kc == 8 && t < 7) {
                // input region's last reader was chunk 7 (fenced by this sync):
                // prefetch next step's inputs now.
                #pragma unroll
                for (int q0 = 0; q0 < 4; ++q0) {
                    int q = tid + 512*q0;
                    int m = q >> 5, c4 = q & 31;
                    int node = wk[m*8 + 7 - (t+1)];
                    cp_async16(Xs + m*G3 + c4*4,       hfeat + (size_t)node*HH + c4*4);
                    cp_async16(Xs + m*G3 + 128 + c4*4,
                               g_ywalk + ((size_t)(t+1)*BB + seq0 + m)*HH + c4*4);
                }
                CP_COMMIT();
            }
            const int kb = kc * 32;
            if (kc < 8) chunk_fma<false>(xr0, xr1, xr2, xr3, Wcur, kb, c0, aR, aZ, aN, aH);
            else        chunk_fma<true >(xr0, xr1, xr2, xr3, Wcur, kb, c0, aR, aZ, aN, aH);
        }

        // epilogue: state rows are warp-private, no sync needed
        float4 br2, bz2, bin, bhn;
        {
            const float4 i0 = *(const float4*)(bih + c0);
            const float4 h0 = *(const float4*)(bhh + c0);
            const float4 i1 = *(const float4*)(bih + 128 + c0);
            const float4 h1 = *(const float4*)(bhh + 128 + c0);
            br2 = make_float4(i0.x+h0.x, i0.y+h0.y, i0.z+h0.z, i0.w+h0.w);
            bz2 = make_float4(i1.x+h1.x, i1.y+h1.y, i1.z+h1.z, i1.w+h1.w);
            bin = *(const float4*)(bih + 256 + c0);
            bhn = *(const float4*)(bhh + 256 + c0);
        }
        #pragma unroll
        for (int i = 0; i < 4; ++i) {
            const int m = my4 + i;
            const int seq = seq0 + m;
            float R[4], Z[4], Ni[4], Nh[4];
            unpack2(aR[i][0], R[0], R[1]);   unpack2(aR[i][1], R[2], R[3]);
            unpack2(aZ[i][0], Z[0], Z[1]);   unpack2(aZ[i][1], Z[2], Z[3]);
            unpack2(aN[i][0], Ni[0], Ni[1]); unpack2(aN[i][1], Ni[2], Ni[3]);
            unpack2(aH[i][0], Nh[0], Nh[1]); unpack2(aH[i][1], Nh[2], Nh[3]);
            float4 hOld = *(const float4*)(Xs + m*G3 + 256 + c0);
            float4 hNew;
            {
                float r = sigmoidf_(R[0] + br2.x);
                float z = sigmoidf_(Z[0] + bz2.x);
                float n = tanhf_(Ni[0] + bin.x + r * (Nh[0] + bhn.x));
                hNew.x = (1.f - z)*n + z*hOld.x;
            }{
                float r = sigmoidf_(R[1] + br2.y);
                float z = sigmoidf_(Z[1] + bz2.y);
                float n = tanhf_(Ni[1] + bin.y + r * (Nh[1] + bhn.y));
                hNew.y = (1.f - z)*n + z*hOld.y;
            }{
                float r = sigmoidf_(R[2] + br2.z);
                float z = sigmoidf_(Z[2] + bz2.z);
                float n = tanhf_(Ni[2] + bin.z + r * (Nh[2] + bhn.z));
                hNew.z = (1.f - z)*n + z*hOld.z;
            }{
                float r = sigmoidf_(R[3] + br2.w);
                float z = sigmoidf_(Z[3] + bz2.w);
                float n = tanhf_(Ni[3] + bin.w + r * (Nh[3] + bhn.w));
                hNew.w = (1.f - z)*n + z*hOld.w;
            }
            *(float4*)(Xs + m*G3 + 256 + c0) = hNew;
            if (t < 7) *(float4*)(g_yseq + (size_t)(t*BB + seq)*HH + c0) = hNew;
            else       *(float4*)(out + (size_t)seq*HH + c0) = hNew;
        }
    }
}

// ---------------- loss -------------------------------------------------------
__global__ void loss_kernel(const float* __restrict__ y0,
                            const int* __restrict__ walks,
                            const int* __restrict__ idxs,
                            const float* __restrict__ b_ss)
{
    const int bid = blockIdx.x;
    const int s   = bid / (SUBN*7);
    const int rem = bid % (SUBN*7);
    const int i   = rem / 7;
    const int tt  = rem % 7;
    const int node = idxs[i];
    const int seq  = s*NN + node;
    __shared__ float yv[128];
    const int tid = threadIdx.x;             // 64 threads
    yv[tid]      = g_yseq[(size_t)(tt*BB + seq)*HH + tid];
    yv[tid + 64] = g_yseq[(size_t)(tt*BB + seq)*HH + tid + 64];
    __syncthreads();

    float acc = b_ss[tid];
    #pragma unroll 8
    for (int k = 0; k < 128; ++k) acc += g_Wsst[k*ORIG_ + tid] * yv[k];

    const int wnode = walks[(size_t)seq*LL + 6 - tt];
    const float yt = y0[(size_t)wnode*ORIG_ + tid];
    const float spP = fmaxf(acc, 0.f) + log1pf(expf(-fabsf(acc)));
    const float spN = spP - acc;
    float ta = yt * spN;
    float tb = (1.f - yt) * spP;
    float ty = yt;

    #pragma unroll
    for (int off = 16; off; off >>= 1) {
        ta += __shfl_down_sync(0xffffffffu, ta, off);
        tb += __shfl_down_sync(0xffffffffu, tb, off);
        ty += __shfl_down_sync(0xffffffffu, ty, off);
    }
    __shared__ float rA[2], rB[2], rY[2];
    if ((tid & 31) == 0) { rA[tid >> 5] = ta; rB[tid >> 5] = tb; rY[tid >> 5] = ty; }
    __syncthreads();
    if (tid == 0) {
        g_partA[bid] = rA[0] + rA[1];
        g_partB[bid] = rB[0] + rB[1];
        g_partY[bid] = rY[0] + rY[1];
    }
}

__global__ void finalize_kernel(float* __restrict__ out, int out_size)
{
    __shared__ float sA[256], sB[256], sY[256];
    const int tid = threadIdx.x;
    float a = 0.f, b = 0.f, y = 0.f;
    for (int i = tid; i < LOSS_BLOCKS; i += 256) {
        a += g_partA[i]; b += g_partB[i]; y += g_partY[i];
    }
    sA[tid] = a; sB[tid] = b; sY[tid] = y;
    __syncthreads();
    for (int off = 128; off; off >>= 1) {
        if (tid < off) { sA[tid] += sA[tid+off]; sB[tid] += sB[tid+off]; sY[tid] += sY[tid+off]; }
        __syncthreads();
    }
    if (tid == 0) out[out_size - 1] = sA[0] / sY[0] + sB[0] / (float)CNT;
}

// ---------------- launch -----------------------------------------------------
extern "C" void kernel_launch(void* const* d_in, const int* in_sizes, int n_in,
                              void* d_out, int out_size)
{
    const float* h_    = (const float*)d_in[0];
    const float* y0    = (const float*)d_in[1];
    const float* Wih_w = (const float*)d_in[2];
    const float* Whh_w = (const float*)d_in[3];
    const float* bih_w = (const float*)d_in[4];
    const float* bhh_w = (const float*)d_in[5];
    const float* Wih   = (const float*)d_in[6];
    const float* Whh   = (const float*)d_in[7];
    const float* bih   = (const float*)d_in[8];
    const float* bhh   = (const float*)d_in[9];
    const float* W_ss  = (const float*)d_in[10];
    const float* b_ss  = (const float*)d_in[11];
    const int*   walks = (const int*)d_in[12];
    const int*   idxs  = (const int*)d_in[13];
    float* out = (float*)d_out;
    (void)in_sizes; (void)n_in;

    cudaFuncSetAttribute(walk_gru_kernel, cudaFuncAttributeMaxDynamicSharedMemorySize, SMEM1B);
    cudaFuncSetAttribute(main_gru_kernel, cudaFuncAttributeMaxDynamicSharedMemorySize, SMEM2B);

    prep_kernel<<<(G3*G3 + 255)/256, 256>>>(Wih_w, bih_w, Whh_w, Wih, Whh, W_ss);
    walk_gru_kernel<<<BB/64, 512, SMEM1B>>>(walks, bhh_w);
    main_gru_kernel<<<BB/64, 512, SMEM2B>>>(walks, h_, bih, bhh, out);
    loss_kernel<<<LOSS_BLOCKS, 64>>>(y0, walks, idxs, b_ss);
    finalize_kernel<<<1, 256>>>(out, out_size);
}